// round 16
// baseline (speedup 1.0000x reference)
#include <cuda_runtime.h>
#include <math.h>

#define Bn 2
#define Tt 4
#define NC 3
#define NK 16
#define Hh 180
#define Ww 320
#define HW (Hh*Ww)
#define CIN_D (Tt*NK)   // 64
#define OUT_C 48
#define SCALE 4

#define LTW 64
#define LTH 16
#define SPW 72
#define SPH 18
#define SPA (SPH*SPW)
#define SPF (SPH*18)

// 8-row tiles (2 px/thread kernels)
#define LTH2 8
#define SPH2 10
#define SPA2 (SPH2*SPW)   // 720
#define SPF2 (SPH2*18)    // 180

typedef unsigned long long ull;

// Scratch (no cudaMalloc allowed)
__device__ float g_hs[Bn*CIN_D*HW];
__device__ float g_c[Bn*NK*HW];
__device__ float g_om[Bn*27*HW];
__device__ float g_def[Bn*NK*HW];

__device__ __forceinline__ float sig_(float v) {
    return __fdividef(1.f, 1.f + __expf(-v));
}
__device__ __forceinline__ float tanh_(float v) {
    float e = __expf(2.f * v);
    return 1.f - __fdividef(2.f, e + 1.f);
}

// ---- packed f32x2 helpers ----
__device__ __forceinline__ ull pack2(float lo, float hi) {
    ull r;
    asm("mov.b64 %0, {%1, %2};" : "=l"(r) : "f"(lo), "f"(hi));
    return r;
}
__device__ __forceinline__ void ffma2(ull& d, ull a, ull b) {
    asm("fma.rn.f32x2 %0, %1, %2, %0;" : "+l"(d) : "l"(a), "l"(b));
}
__device__ __forceinline__ float2 unpack2(ull v) {
    float2 f;
    asm("mov.b64 {%0, %1}, %2;" : "=f"(f.x), "=f"(f.y) : "l"(v));
    return f;
}

__device__ __forceinline__ void cp_async16(float* dst_smem, const float* src) {
    unsigned d = (unsigned)__cvta_generic_to_shared(dst_smem);
    asm volatile("cp.async.cg.shared.global [%0], [%1], 16;" :: "r"(d), "l"(src));
}
#define CP_COMMIT() asm volatile("cp.async.commit_group;" ::: "memory")
#define CP_WAIT0()  asm volatile("cp.async.wait_group 0;" ::: "memory")

// stage one conv patch (gx in [bx-4, bx+68)), 18-row version
__device__ __forceinline__ void stage_patch16(float* dst, const float* src,
                                              int bx, int by, int tid)
{
    #pragma unroll
    for (int i = tid; i < SPF; i += 256) {
        int pr = i / 18, f = i - pr * 18;
        int gy = by - 1 + pr;
        int gxf = bx - 4 + f * 4;
        float* d = dst + pr * SPW + f * 4;
        if (gy >= 0 && gy < Hh && gxf >= 0 && gxf + 4 <= Ww)
            cp_async16(d, src + gy * Ww + gxf);
        else
            *(float4*)d = make_float4(0.f, 0.f, 0.f, 0.f);
    }
}

// 10-row version for 8-row tiles
__device__ __forceinline__ void stage_patch16_8(float* dst, const float* src,
                                                int bx, int by, int tid)
{
    #pragma unroll
    for (int i = tid; i < SPF2; i += 256) {
        int pr = i / 18, f = i - pr * 18;
        int gy = by - 1 + pr;
        int gxf = bx - 4 + f * 4;
        float* d = dst + pr * SPW + f * 4;
        if (gy >= 0 && gy < Hh && gxf >= 0 && gxf + 4 <= Ww)
            cp_async16(d, src + gy * Ww + gxf);
        else
            *(float4*)d = make_float4(0.f, 0.f, 0.f, 0.f);
    }
}

// 5-pair (10-output) variant, weight stride 12 floats/tap (offmask)
__device__ __forceinline__ void conv_accum_o(ull acc2[5][4], const float* patch,
                                             const float* wc, int tx, int ty)
{
    #pragma unroll
    for (int tr = 0; tr < 3; tr++) {
        const float2* rp = (const float2*)(patch + (ty + tr) * SPW + tx * 4 + 2);
        float2 a = rp[0], b = rp[1], c = rp[2], d = rp[3];
        float v[6] = {a.y, b.x, b.y, c.x, c.y, d.x};
        ull vv[6];
        #pragma unroll
        for (int j = 0; j < 6; j++) vv[j] = pack2(v[j], v[j]);
        #pragma unroll
        for (int tc = 0; tc < 3; tc++) {
            const float* wt = wc + (tr * 3 + tc) * 12;
            ulonglong2 wa = *(const ulonglong2*)wt;
            ulonglong2 wb = *(const ulonglong2*)(wt + 4);
            ull wp4 = *(const ull*)(wt + 8);
            ull wp[5] = {wa.x, wa.y, wb.x, wb.y, wp4};
            #pragma unroll
            for (int q = 0; q < 5; q++) {
                #pragma unroll
                for (int px = 0; px < 4; px++)
                    ffma2(acc2[q][px], vv[tc + px], wp[q]);
            }
        }
    }
}

// 4-px x 8-output variant for lstm (tx in [0,16)); weight stride 8 floats/tap.
// Patch cols used: tx*4+3 .. tx*4+8 (gx = x-1 .. x+4), same as conv_accum_o.
__device__ __forceinline__ void conv_accum_l(ull acc2[4][4], const float* patch,
                                             const float* wc, int tx, int ty)
{
    #pragma unroll
    for (int tr = 0; tr < 3; tr++) {
        const float2* rp = (const float2*)(patch + (ty + tr) * SPW + tx * 4 + 2);
        float2 a = rp[0], b = rp[1], c = rp[2], d = rp[3];
        float v[6] = {a.y, b.x, b.y, c.x, c.y, d.x};
        ull vv[6];
        #pragma unroll
        for (int j = 0; j < 6; j++) vv[j] = pack2(v[j], v[j]);
        #pragma unroll
        for (int tc = 0; tc < 3; tc++) {
            const ulonglong2* w2 = (const ulonglong2*)(wc + (tr * 3 + tc) * 8);
            #pragma unroll
            for (int h = 0; h < 2; h++) {
                ulonglong2 w = w2[h];
                #pragma unroll
                for (int px = 0; px < 4; px++) {
                    ffma2(acc2[2*h][px],   vv[tc + px], w.x);
                    ffma2(acc2[2*h+1][px], vv[tc + px], w.y);
                }
            }
        }
    }
}

// 2-px variant (tx in [0,32)), weight stride 16 (outconv)
__device__ __forceinline__ void conv_accum_p2(ull acc2[8][2], const float* patch,
                                              const float* wc, int tx, int ty)
{
    #pragma unroll
    for (int tr = 0; tr < 3; tr++) {
        const float2* rp = (const float2*)(patch + (ty + tr) * SPW + tx * 2 + 2);
        float2 a = rp[0], b = rp[1], c = rp[2];
        float v[4] = {a.y, b.x, b.y, c.x};
        ull vv[4];
        #pragma unroll
        for (int j = 0; j < 4; j++) vv[j] = pack2(v[j], v[j]);
        #pragma unroll
        for (int tc = 0; tc < 3; tc++) {
            const ulonglong2* w2 = (const ulonglong2*)(wc + (tr * 3 + tc) * 16);
            #pragma unroll
            for (int h = 0; h < 4; h++) {
                ulonglong2 w = w2[h];
                ffma2(acc2[2*h][0],   vv[tc],     w.x);
                ffma2(acc2[2*h][1],   vv[tc + 1], w.x);
                ffma2(acc2[2*h+1][0], vv[tc],     w.y);
                ffma2(acc2[2*h+1][1], vv[tc + 1], w.y);
            }
        }
    }
}

// ---------------------------------------------------------------------------
// ConvLSTM step. block (16,16); thread = 4 px, 8 outputs (4 gates x 2 k).
// blockIdx.z = b*8 + kg (kg selects k pair). 3 CTAs/SM.
// ---------------------------------------------------------------------------
__global__ __launch_bounds__(256, 3)
void lstm_step_kernel(const float* __restrict__ X,
                      const float* __restrict__ lw,
                      const float* __restrict__ lb,
                      const float* __restrict__ Wci,
                      const float* __restrict__ Wcf,
                      const float* __restrict__ Wco,
                      int t)
{
    __shared__ __align__(16) float sw[19 * 9 * 8];
    __shared__ __align__(16) float sp[2][4 * SPA];
    __shared__ float sb[8];

    const int tx = threadIdx.x, ty = threadIdx.y;
    const int tid = ty * 16 + tx;
    const int bz = blockIdx.z;
    const int b = bz >> 3, kg = bz & 7;
    const int bx = blockIdx.x * LTW, by = blockIdx.y * LTH;
    const int x0 = bx + tx * 4, y = by + ty;

    // lo = gate*2 + kk -> global row = gate*16 + kg*2 + kk
    for (int i = tid; i < 19 * 9 * 8; i += 256) {
        int lo = i / 171, rest = i - lo * 171;
        int row = (lo >> 1) * NK + kg * 2 + (lo & 1);
        sw[rest * 8 + lo] = lw[row * 171 + rest];
    }
    if (tid < 8)
        sb[tid] = lb[(tid >> 1) * NK + kg * 2 + (tid & 1)];

    const int ncin = (t == 0) ? NC : (NC + NK);
    const int nb = (ncin + 3) >> 2;

    #define LSTM_SRC(c) ((c) < NC \
        ? (X + (((size_t)b * Tt + t) * NC + (c)) * HW) \
        : (g_hs + ((size_t)b * CIN_D + (t - 1) * NK + ((c) - NC)) * HW))

    #pragma unroll
    for (int cc = 0; cc < 4; cc++)
        if (cc < ncin) stage_patch16(sp[0] + cc * SPA, LSTM_SRC(cc), bx, by, tid);
    CP_COMMIT();

    __syncthreads();   // sb/sw visible

    ull acc2[4][4];
    #pragma unroll
    for (int q = 0; q < 4; q++) {
        ull bv = pack2(sb[2*q], sb[2*q+1]);
        #pragma unroll
        for (int px = 0; px < 4; px++) acc2[q][px] = bv;
    }

    for (int cb = 0; cb < nb; cb++) {
        int cur = cb & 1;
        CP_WAIT0();
        __syncthreads();
        if (cb + 1 < nb) {
            int cn = (cb + 1) * 4;
            #pragma unroll
            for (int cc = 0; cc < 4; cc++)
                if (cn + cc < ncin)
                    stage_patch16(sp[cur ^ 1] + cc * SPA, LSTM_SRC(cn + cc), bx, by, tid);
        }
        CP_COMMIT();
        int c0 = cb * 4;
        #pragma unroll
        for (int cc = 0; cc < 4; cc++)
            if (c0 + cc < ncin)
                conv_accum_l(acc2, sp[cur] + cc * SPA, sw + (c0 + cc) * 72, tx, ty);
    }
    #undef LSTM_SRC

    if (y < Hh) {
        const int p = y * Ww + x0;
        // accf[lo][px], lo = gate*2+kk
        float accf[8][4];
        #pragma unroll
        for (int q = 0; q < 4; q++) {
            #pragma unroll
            for (int px = 0; px < 4; px++) {
                float2 u = unpack2(acc2[q][px]);
                accf[2*q][px] = u.x;
                accf[2*q+1][px] = u.y;
            }
        }
        #pragma unroll
        for (int kk = 0; kk < 2; kk++) {
            int k = kg * 2 + kk;
            float ci4[4], cf4[4], co4[4], cp4[4], cn4[4], h4[4];
            *(float4*)ci4 = *(const float4*)(Wci + k * HW + p);
            *(float4*)cf4 = *(const float4*)(Wcf + k * HW + p);
            *(float4*)co4 = *(const float4*)(Wco + k * HW + p);
            if (t == 0) {
                #pragma unroll
                for (int px = 0; px < 4; px++) cp4[px] = 0.f;
            } else {
                *(float4*)cp4 = *(const float4*)(g_c + ((size_t)b * NK + k) * HW + p);
            }
            #pragma unroll
            for (int px = 0; px < 4; px++) {
                float cprev = cp4[px];
                float i_ = sig_(accf[kk][px]     + ci4[px] * cprev);
                float f_ = sig_(accf[2 + kk][px] + cf4[px] * cprev);
                float cn = f_ * cprev + i_ * tanh_(accf[4 + kk][px]);
                float o_ = sig_(accf[6 + kk][px] + co4[px] * cn);
                cn4[px] = cn;
                h4[px] = o_ * tanh_(cn);
            }
            *(float4*)(g_c + ((size_t)b * NK + k) * HW + p) = *(float4*)cn4;
            *(float4*)(g_hs + ((size_t)b * CIN_D + t * NK + k) * HW + p) = *(float4*)h4;
        }
    }
}

// ---------------------------------------------------------------------------
// Offset+mask conv 64 -> 27. 3 groups of 10 computed / 9 stored. (R12 winner)
// ---------------------------------------------------------------------------
__global__ __launch_bounds__(256, 3)
void offmask_kernel(const float* __restrict__ off_w,
                    const float* __restrict__ off_b,
                    const float* __restrict__ mod_w,
                    const float* __restrict__ mod_b)
{
    __shared__ __align__(16) float sw[12 * 576];
    __shared__ __align__(16) float sp[2][4 * SPA];
    __shared__ float sb[12];

    const int tx = threadIdx.x, ty = threadIdx.y;
    const int tid = ty * 16 + tx;
    const int bz = blockIdx.z;
    const int b = bz / 3, g = bz - b * 3;
    const int base = g * 9;
    const int bx = blockIdx.x * LTW, by = blockIdx.y * LTH;
    const int x0 = bx + tx * 4, y = by + ty;

    for (int i = tid; i < 12 * 576; i += 256) {
        int rest = i / 12, lo = i - rest * 12;
        int oc = base + lo;
        float v = 0.f;
        if (lo < 10 && oc < 27) {
            if (oc < 18) v = off_w[(size_t)oc * 576 + rest];
            else v = mod_w[(size_t)(oc - 18) * 576 + rest];
        }
        sw[rest * 12 + lo] = v;
    }
    if (tid < 12) {
        int oc = base + tid;
        float v = 0.f;
        if (tid < 10 && oc < 27) v = (oc < 18) ? off_b[oc] : mod_b[oc - 18];
        sb[tid] = v;
    }

    const float* xb = g_hs + (size_t)b * CIN_D * HW;

    #pragma unroll
    for (int cc = 0; cc < 4; cc++)
        stage_patch16(sp[0] + cc * SPA, xb + (size_t)cc * HW, bx, by, tid);
    CP_COMMIT();

    __syncthreads();

    ull acc2[5][4];
    #pragma unroll
    for (int q = 0; q < 5; q++) {
        ull bv = pack2(sb[2*q], sb[2*q+1]);
        #pragma unroll
        for (int px = 0; px < 4; px++) acc2[q][px] = bv;
    }

    for (int cb = 0; cb < 16; cb++) {
        int cur = cb & 1;
        CP_WAIT0();
        __syncthreads();
        if (cb + 1 < 16) {
            int cn = (cb + 1) * 4;
            #pragma unroll
            for (int cc = 0; cc < 4; cc++)
                stage_patch16(sp[cur ^ 1] + cc * SPA, xb + (size_t)(cn + cc) * HW, bx, by, tid);
        }
        CP_COMMIT();
        int c0 = cb * 4;
        #pragma unroll
        for (int cc = 0; cc < 4; cc++)
            conv_accum_o(acc2, sp[cur] + cc * SPA, sw + (c0 + cc) * 108, tx, ty);
    }

    if (y < Hh) {
        const int p = y * Ww + x0;
        #pragma unroll
        for (int lo = 0; lo < 9; lo++) {
            int oc = base + lo;
            float o4[4];
            #pragma unroll
            for (int px = 0; px < 4; px++) {
                float2 u = unpack2(acc2[lo >> 1][px]);
                o4[px] = (lo & 1) ? u.y : u.x;
            }
            if (oc >= 18) {
                #pragma unroll
                for (int px = 0; px < 4; px++) o4[px] = 2.f * sig_(o4[px]);
            }
            *(float4*)(g_om + ((size_t)b * 27 + oc) * HW + p) = *(float4*)o4;
        }
    }
}

// ---------------------------------------------------------------------------
// Modulated deformable conv. (R13 version, 3 CTAs/SM)
// ---------------------------------------------------------------------------
__global__ __launch_bounds__(256, 3)
void deform_kernel(const float* __restrict__ def_w,
                   const float* __restrict__ def_b)
{
    __shared__ __align__(16) float swd[NK * CIN_D * 9];
    __shared__ float sb[NK];

    const int bx = blockIdx.x * 32, by = blockIdx.y * 8;
    const int b = blockIdx.z;
    const int tx = threadIdx.x, ty = threadIdx.y;
    const int tid = ty * 32 + tx;

    for (int i = tid; i < NK * CIN_D * 9; i += 256) {
        int o = i / 576, rest = i - o * 576;
        swd[rest * 16 + o] = def_w[i];
    }
    if (tid < NK) sb[tid] = def_b[tid];
    __syncthreads();

    const int x = bx + tx, y = by + ty;
    if (y >= Hh) return;
    const int p = y * Ww + x;

    const float* xb = g_hs + (size_t)b * CIN_D * HW;
    const float* om = g_om + (size_t)b * 27 * HW;

    ull acc2[8];
    #pragma unroll
    for (int q = 0; q < 8; q++) acc2[q] = pack2(sb[2*q], sb[2*q+1]);

    #pragma unroll
    for (int j = 0; j < 9; j++) {
        int ky = j / 3, kx = j - ky * 3;
        float dy = om[(2 * j) * HW + p];
        float dx = om[(2 * j + 1) * HW + p];
        float m  = om[(18 + j) * HW + p];
        float py = (float)(y - 1 + ky) + dy;
        float px_ = (float)(x - 1 + kx) + dx;
        float y0f = floorf(py), x0f = floorf(px_);
        float wy = py - y0f, wx = px_ - x0f;
        int y0 = (int)y0f, x0 = (int)x0f;
        int y1 = y0 + 1,   x1 = x0 + 1;
        float vy0 = (y0 >= 0 && y0 < Hh) ? 1.f : 0.f;
        float vy1 = (y1 >= 0 && y1 < Hh) ? 1.f : 0.f;
        float vx0 = (x0 >= 0 && x0 < Ww) ? 1.f : 0.f;
        float vx1 = (x1 >= 0 && x1 < Ww) ? 1.f : 0.f;
        int y0c = min(max(y0, 0), Hh - 1), y1c = min(max(y1, 0), Hh - 1);
        int x0c = min(max(x0, 0), Ww - 1), x1c = min(max(x1, 0), Ww - 1);
        float w00 = (1.f - wy) * (1.f - wx) * vy0 * vx0 * m;
        float w01 = (1.f - wy) * wx         * vy0 * vx1 * m;
        float w10 = wy * (1.f - wx)         * vy1 * vx0 * m;
        float w11 = wy * wx                 * vy1 * vx1 * m;
        int o00 = y0c * Ww + x0c, o01 = y0c * Ww + x1c;
        int o10 = y1c * Ww + x0c, o11 = y1c * Ww + x1c;

        #pragma unroll 4
        for (int c = 0; c < CIN_D; c++) {
            const float* pc_ = xb + (size_t)c * HW;
            float s = w00 * pc_[o00] + w01 * pc_[o01]
                    + w10 * pc_[o10] + w11 * pc_[o11];
            ull ss = pack2(s, s);
            const ulonglong2* w2 = (const ulonglong2*)(swd + (c * 9 + j) * 16);
            ulonglong2 wa = w2[0], wb = w2[1], wc2 = w2[2], wd = w2[3];
            ffma2(acc2[0], ss, wa.x); ffma2(acc2[1], ss, wa.y);
            ffma2(acc2[2], ss, wb.x); ffma2(acc2[3], ss, wb.y);
            ffma2(acc2[4], ss, wc2.x); ffma2(acc2[5], ss, wc2.y);
            ffma2(acc2[6], ss, wd.x); ffma2(acc2[7], ss, wd.y);
        }
    }

    #pragma unroll
    for (int q = 0; q < 8; q++) {
        float2 u = unpack2(acc2[q]);
        g_def[((size_t)b * NK + 2*q    ) * HW + p] = u.x;
        g_def[((size_t)b * NK + 2*q + 1) * HW + p] = u.y;
    }
}

// ---------------------------------------------------------------------------
// Output conv 16 -> 48 + pixel shuffle + clip. (R13 version, 2px, 3 CTAs/SM)
// ---------------------------------------------------------------------------
__global__ __launch_bounds__(256, 3)
void outconv_kernel(const float* __restrict__ out_w,
                    const float* __restrict__ out_b,
                    float* __restrict__ out)
{
    __shared__ __align__(16) float sw[16 * 144];
    __shared__ __align__(16) float sp[2][4 * SPA2];
    __shared__ float sb[16];

    const int tx = threadIdx.x, ty = threadIdx.y;
    const int tid = ty * 32 + tx;
    const int bz = blockIdx.z;
    const int b = bz / 3, g3 = bz - b * 3;
    const int base = g3 * 16;
    const int bx = blockIdx.x * LTW, by = blockIdx.y * LTH2;
    const int x0 = bx + tx * 2, y = by + ty;

    for (int i = tid; i < 16 * 144; i += 256) {
        int lo = i / 144, rest = i - lo * 144;
        sw[rest * 16 + lo] = out_w[(size_t)(base + lo) * 144 + rest];
    }
    if (tid < 16) sb[tid] = out_b[base + tid];

    const float* xb = g_def + (size_t)b * NK * HW;

    #pragma unroll
    for (int cc = 0; cc < 4; cc++)
        stage_patch16_8(sp[0] + cc * SPA2, xb + (size_t)cc * HW, bx, by, tid);
    CP_COMMIT();

    __syncthreads();

    ull acc2[8][2];
    #pragma unroll
    for (int q = 0; q < 8; q++) {
        ull bv = pack2(sb[2*q], sb[2*q+1]);
        acc2[q][0] = bv; acc2[q][1] = bv;
    }

    for (int cb = 0; cb < 4; cb++) {
        int cur = cb & 1;
        CP_WAIT0();
        __syncthreads();
        if (cb + 1 < 4) {
            int cn = (cb + 1) * 4;
            #pragma unroll
            for (int cc = 0; cc < 4; cc++)
                stage_patch16_8(sp[cur ^ 1] + cc * SPA2, xb + (size_t)(cn + cc) * HW, bx, by, tid);
        }
        CP_COMMIT();
        int c0 = cb * 4;
        #pragma unroll
        for (int cc = 0; cc < 4; cc++)
            conv_accum_p2(acc2, sp[cur] + cc * SPA2, sw + (c0 + cc) * 144, tx, ty);
    }

    if (y < Hh) {
        #pragma unroll
        for (int lo = 0; lo < 16; lo++) {
            int oc = base + lo;
            int cch = oc >> 4, rem = oc & 15;
            int r1 = rem >> 2, r2 = rem & 3;
            float2 u = unpack2(acc2[lo >> 1][0]);
            float2 u2 = unpack2(acc2[lo >> 1][1]);
            float v0 = (lo & 1) ? u.y : u.x;
            float v1 = (lo & 1) ? u2.y : u2.x;
            v0 = fminf(fmaxf(v0, 0.f), 255.f);
            v1 = fminf(fmaxf(v1, 0.f), 255.f);
            size_t rowbase = (((size_t)b * NC + cch) * (Hh * SCALE) + (y * SCALE + r1))
                             * (size_t)(Ww * SCALE);
            out[rowbase + (x0 * SCALE + r2)] = v0;
            out[rowbase + ((x0 + 1) * SCALE + r2)] = v1;
        }
    }
}

// ---------------------------------------------------------------------------
extern "C" void kernel_launch(void* const* d_in, const int* in_sizes, int n_in,
                              void* d_out, int out_size)
{
    const float* X      = (const float*)d_in[0];
    const float* lstm_w = (const float*)d_in[1];
    const float* lstm_b = (const float*)d_in[2];
    const float* W_ci   = (const float*)d_in[3];
    const float* W_cf   = (const float*)d_in[4];
    const float* W_co   = (const float*)d_in[5];
    const float* off_w  = (const float*)d_in[6];
    const float* off_b  = (const float*)d_in[7];
    const float* mod_w  = (const float*)d_in[8];
    const float* mod_b  = (const float*)d_in[9];
    const float* def_w  = (const float*)d_in[10];
    const float* def_b  = (const float*)d_in[11];
    const float* out_w  = (const float*)d_in[12];
    const float* out_b  = (const float*)d_in[13];
    float* out = (float*)d_out;

    dim3 blk16(16, 16);
    dim3 grid_lstm(Ww / LTW, (Hh + LTH - 1) / LTH, Bn * 8);

    dim3 grid_om(Ww / LTW, (Hh + LTH - 1) / LTH, Bn * 3);

    dim3 blk32x8(32, 8);
    dim3 grid_oc8(Ww / LTW, (Hh + LTH2 - 1) / LTH2, Bn * 3);

    for (int t = 0; t < Tt; t++)
        lstm_step_kernel<<<grid_lstm, blk16>>>(X, lstm_w, lstm_b, W_ci, W_cf, W_co, t);

    offmask_kernel<<<grid_om, blk16>>>(off_w, off_b, mod_w, mod_b);

    dim3 grid_def(Ww / 32, (Hh + 7) / 8, Bn);
    deform_kernel<<<grid_def, blk32x8>>>(def_w, def_b);

    outconv_kernel<<<grid_oc8, blk32x8>>>(out_w, out_b, out);
}

// round 17
// speedup vs baseline: 1.0613x; 1.0613x over previous
#include <cuda_runtime.h>
#include <math.h>

#define Bn 2
#define Tt 4
#define NC 3
#define NK 16
#define Hh 180
#define Ww 320
#define HW (Hh*Ww)
#define CIN_D (Tt*NK)   // 64
#define OUT_C 48
#define SCALE 4

#define LTW 64
#define LTH 16
#define SPW 72
#define SPH 18
#define SPA (SPH*SPW)
#define SPF (SPH*18)

// 8-row tiles (2 px/thread kernels)
#define LTH2 8
#define SPH2 10
#define SPA2 (SPH2*SPW)   // 720
#define SPF2 (SPH2*18)    // 180

typedef unsigned long long ull;

// Scratch (no cudaMalloc allowed)
__device__ float g_hs[Bn*CIN_D*HW];
__device__ float g_c[Bn*NK*HW];
__device__ float g_om[Bn*27*HW];
__device__ float g_def[Bn*NK*HW];

__device__ __forceinline__ float sig_(float v) {
    return __fdividef(1.f, 1.f + __expf(-v));
}
__device__ __forceinline__ float tanh_(float v) {
    float e = __expf(2.f * v);
    return 1.f - __fdividef(2.f, e + 1.f);
}

// ---- packed f32x2 helpers ----
__device__ __forceinline__ ull pack2(float lo, float hi) {
    ull r;
    asm("mov.b64 %0, {%1, %2};" : "=l"(r) : "f"(lo), "f"(hi));
    return r;
}
__device__ __forceinline__ void ffma2(ull& d, ull a, ull b) {
    asm("fma.rn.f32x2 %0, %1, %2, %0;" : "+l"(d) : "l"(a), "l"(b));
}
__device__ __forceinline__ float2 unpack2(ull v) {
    float2 f;
    asm("mov.b64 {%0, %1}, %2;" : "=f"(f.x), "=f"(f.y) : "l"(v));
    return f;
}

__device__ __forceinline__ void cp_async16(float* dst_smem, const float* src) {
    unsigned d = (unsigned)__cvta_generic_to_shared(dst_smem);
    asm volatile("cp.async.cg.shared.global [%0], [%1], 16;" :: "r"(d), "l"(src));
}
#define CP_COMMIT() asm volatile("cp.async.commit_group;" ::: "memory")
#define CP_WAIT0()  asm volatile("cp.async.wait_group 0;" ::: "memory")

// stage one conv patch (gx in [bx-4, bx+68)), 18-row version
__device__ __forceinline__ void stage_patch16(float* dst, const float* src,
                                              int bx, int by, int tid)
{
    #pragma unroll
    for (int i = tid; i < SPF; i += 256) {
        int pr = i / 18, f = i - pr * 18;
        int gy = by - 1 + pr;
        int gxf = bx - 4 + f * 4;
        float* d = dst + pr * SPW + f * 4;
        if (gy >= 0 && gy < Hh && gxf >= 0 && gxf + 4 <= Ww)
            cp_async16(d, src + gy * Ww + gxf);
        else
            *(float4*)d = make_float4(0.f, 0.f, 0.f, 0.f);
    }
}

// 10-row version for 8-row tiles
__device__ __forceinline__ void stage_patch16_8(float* dst, const float* src,
                                                int bx, int by, int tid)
{
    #pragma unroll
    for (int i = tid; i < SPF2; i += 256) {
        int pr = i / 18, f = i - pr * 18;
        int gy = by - 1 + pr;
        int gxf = bx - 4 + f * 4;
        float* d = dst + pr * SPW + f * 4;
        if (gy >= 0 && gy < Hh && gxf >= 0 && gxf + 4 <= Ww)
            cp_async16(d, src + gy * Ww + gxf);
        else
            *(float4*)d = make_float4(0.f, 0.f, 0.f, 0.f);
    }
}

// 5-pair (10-output) variant, weight stride 12 floats/tap (offmask)
__device__ __forceinline__ void conv_accum_o(ull acc2[5][4], const float* patch,
                                             const float* wc, int tx, int ty)
{
    #pragma unroll
    for (int tr = 0; tr < 3; tr++) {
        const float2* rp = (const float2*)(patch + (ty + tr) * SPW + tx * 4 + 2);
        float2 a = rp[0], b = rp[1], c = rp[2], d = rp[3];
        float v[6] = {a.y, b.x, b.y, c.x, c.y, d.x};
        ull vv[6];
        #pragma unroll
        for (int j = 0; j < 6; j++) vv[j] = pack2(v[j], v[j]);
        #pragma unroll
        for (int tc = 0; tc < 3; tc++) {
            const float* wt = wc + (tr * 3 + tc) * 12;
            ulonglong2 wa = *(const ulonglong2*)wt;
            ulonglong2 wb = *(const ulonglong2*)(wt + 4);
            ull wp4 = *(const ull*)(wt + 8);
            ull wp[5] = {wa.x, wa.y, wb.x, wb.y, wp4};
            #pragma unroll
            for (int q = 0; q < 5; q++) {
                #pragma unroll
                for (int px = 0; px < 4; px++)
                    ffma2(acc2[q][px], vv[tc + px], wp[q]);
            }
        }
    }
}

// 4-px x 8-output variant for lstm (tx in [0,16)); weight stride 8 floats/tap.
__device__ __forceinline__ void conv_accum_l(ull acc2[4][4], const float* patch,
                                             const float* wc, int tx, int ty)
{
    #pragma unroll
    for (int tr = 0; tr < 3; tr++) {
        const float2* rp = (const float2*)(patch + (ty + tr) * SPW + tx * 4 + 2);
        float2 a = rp[0], b = rp[1], c = rp[2], d = rp[3];
        float v[6] = {a.y, b.x, b.y, c.x, c.y, d.x};
        ull vv[6];
        #pragma unroll
        for (int j = 0; j < 6; j++) vv[j] = pack2(v[j], v[j]);
        #pragma unroll
        for (int tc = 0; tc < 3; tc++) {
            const ulonglong2* w2 = (const ulonglong2*)(wc + (tr * 3 + tc) * 8);
            #pragma unroll
            for (int h = 0; h < 2; h++) {
                ulonglong2 w = w2[h];
                #pragma unroll
                for (int px = 0; px < 4; px++) {
                    ffma2(acc2[2*h][px],   vv[tc + px], w.x);
                    ffma2(acc2[2*h+1][px], vv[tc + px], w.y);
                }
            }
        }
    }
}

// 2-px variant (tx in [0,32)), weight stride 16 (outconv)
__device__ __forceinline__ void conv_accum_p2(ull acc2[8][2], const float* patch,
                                              const float* wc, int tx, int ty)
{
    #pragma unroll
    for (int tr = 0; tr < 3; tr++) {
        const float2* rp = (const float2*)(patch + (ty + tr) * SPW + tx * 2 + 2);
        float2 a = rp[0], b = rp[1], c = rp[2];
        float v[4] = {a.y, b.x, b.y, c.x};
        ull vv[4];
        #pragma unroll
        for (int j = 0; j < 4; j++) vv[j] = pack2(v[j], v[j]);
        #pragma unroll
        for (int tc = 0; tc < 3; tc++) {
            const ulonglong2* w2 = (const ulonglong2*)(wc + (tr * 3 + tc) * 16);
            #pragma unroll
            for (int h = 0; h < 4; h++) {
                ulonglong2 w = w2[h];
                ffma2(acc2[2*h][0],   vv[tc],     w.x);
                ffma2(acc2[2*h][1],   vv[tc + 1], w.x);
                ffma2(acc2[2*h+1][0], vv[tc],     w.y);
                ffma2(acc2[2*h+1][1], vv[tc + 1], w.y);
            }
        }
    }
}

// ---------------------------------------------------------------------------
// ConvLSTM step. block (16,16); thread = 4 px, 8 outputs (4 gates x 2 k).
// blockIdx.z = b*8 + kg. 4 CTAs/SM target.
// ---------------------------------------------------------------------------
__global__ __launch_bounds__(256, 4)
void lstm_step_kernel(const float* __restrict__ X,
                      const float* __restrict__ lw,
                      const float* __restrict__ lb,
                      const float* __restrict__ Wci,
                      const float* __restrict__ Wcf,
                      const float* __restrict__ Wco,
                      int t)
{
    __shared__ __align__(16) float sw[19 * 9 * 8];
    __shared__ __align__(16) float sp[2][4 * SPA];
    __shared__ float sb[8];

    const int tx = threadIdx.x, ty = threadIdx.y;
    const int tid = ty * 16 + tx;
    const int bz = blockIdx.z;
    const int b = bz >> 3, kg = bz & 7;
    const int bx = blockIdx.x * LTW, by = blockIdx.y * LTH;
    const int x0 = bx + tx * 4, y = by + ty;

    for (int i = tid; i < 19 * 9 * 8; i += 256) {
        int lo = i / 171, rest = i - lo * 171;
        int row = (lo >> 1) * NK + kg * 2 + (lo & 1);
        sw[rest * 8 + lo] = lw[row * 171 + rest];
    }
    if (tid < 8)
        sb[tid] = lb[(tid >> 1) * NK + kg * 2 + (tid & 1)];

    const int ncin = (t == 0) ? NC : (NC + NK);
    const int nb = (ncin + 3) >> 2;

    #define LSTM_SRC(c) ((c) < NC \
        ? (X + (((size_t)b * Tt + t) * NC + (c)) * HW) \
        : (g_hs + ((size_t)b * CIN_D + (t - 1) * NK + ((c) - NC)) * HW))

    #pragma unroll
    for (int cc = 0; cc < 4; cc++)
        if (cc < ncin) stage_patch16(sp[0] + cc * SPA, LSTM_SRC(cc), bx, by, tid);
    CP_COMMIT();

    __syncthreads();   // sb/sw visible

    ull acc2[4][4];
    #pragma unroll
    for (int q = 0; q < 4; q++) {
        ull bv = pack2(sb[2*q], sb[2*q+1]);
        #pragma unroll
        for (int px = 0; px < 4; px++) acc2[q][px] = bv;
    }

    for (int cb = 0; cb < nb; cb++) {
        int cur = cb & 1;
        CP_WAIT0();
        __syncthreads();
        if (cb + 1 < nb) {
            int cn = (cb + 1) * 4;
            #pragma unroll
            for (int cc = 0; cc < 4; cc++)
                if (cn + cc < ncin)
                    stage_patch16(sp[cur ^ 1] + cc * SPA, LSTM_SRC(cn + cc), bx, by, tid);
        }
        CP_COMMIT();
        int c0 = cb * 4;
        #pragma unroll
        for (int cc = 0; cc < 4; cc++)
            if (c0 + cc < ncin)
                conv_accum_l(acc2, sp[cur] + cc * SPA, sw + (c0 + cc) * 72, tx, ty);
    }
    #undef LSTM_SRC

    if (y < Hh) {
        const int p = y * Ww + x0;
        float accf[8][4];
        #pragma unroll
        for (int q = 0; q < 4; q++) {
            #pragma unroll
            for (int px = 0; px < 4; px++) {
                float2 u = unpack2(acc2[q][px]);
                accf[2*q][px] = u.x;
                accf[2*q+1][px] = u.y;
            }
        }
        #pragma unroll
        for (int kk = 0; kk < 2; kk++) {
            int k = kg * 2 + kk;
            float ci4[4], cf4[4], co4[4], cp4[4], cn4[4], h4[4];
            *(float4*)ci4 = *(const float4*)(Wci + k * HW + p);
            *(float4*)cf4 = *(const float4*)(Wcf + k * HW + p);
            *(float4*)co4 = *(const float4*)(Wco + k * HW + p);
            if (t == 0) {
                #pragma unroll
                for (int px = 0; px < 4; px++) cp4[px] = 0.f;
            } else {
                *(float4*)cp4 = *(const float4*)(g_c + ((size_t)b * NK + k) * HW + p);
            }
            #pragma unroll
            for (int px = 0; px < 4; px++) {
                float cprev = cp4[px];
                float i_ = sig_(accf[kk][px]     + ci4[px] * cprev);
                float f_ = sig_(accf[2 + kk][px] + cf4[px] * cprev);
                float cn = f_ * cprev + i_ * tanh_(accf[4 + kk][px]);
                float o_ = sig_(accf[6 + kk][px] + co4[px] * cn);
                cn4[px] = cn;
                h4[px] = o_ * tanh_(cn);
            }
            *(float4*)(g_c + ((size_t)b * NK + k) * HW + p) = *(float4*)cn4;
            *(float4*)(g_hs + ((size_t)b * CIN_D + t * NK + k) * HW + p) = *(float4*)h4;
        }
    }
}

// ---------------------------------------------------------------------------
// Offset+mask conv 64 -> 27. 3 groups of 10 computed / 9 stored. (R12 winner)
// ---------------------------------------------------------------------------
__global__ __launch_bounds__(256, 3)
void offmask_kernel(const float* __restrict__ off_w,
                    const float* __restrict__ off_b,
                    const float* __restrict__ mod_w,
                    const float* __restrict__ mod_b)
{
    __shared__ __align__(16) float sw[12 * 576];
    __shared__ __align__(16) float sp[2][4 * SPA];
    __shared__ float sb[12];

    const int tx = threadIdx.x, ty = threadIdx.y;
    const int tid = ty * 16 + tx;
    const int bz = blockIdx.z;
    const int b = bz / 3, g = bz - b * 3;
    const int base = g * 9;
    const int bx = blockIdx.x * LTW, by = blockIdx.y * LTH;
    const int x0 = bx + tx * 4, y = by + ty;

    for (int i = tid; i < 12 * 576; i += 256) {
        int rest = i / 12, lo = i - rest * 12;
        int oc = base + lo;
        float v = 0.f;
        if (lo < 10 && oc < 27) {
            if (oc < 18) v = off_w[(size_t)oc * 576 + rest];
            else v = mod_w[(size_t)(oc - 18) * 576 + rest];
        }
        sw[rest * 12 + lo] = v;
    }
    if (tid < 12) {
        int oc = base + tid;
        float v = 0.f;
        if (tid < 10 && oc < 27) v = (oc < 18) ? off_b[oc] : mod_b[oc - 18];
        sb[tid] = v;
    }

    const float* xb = g_hs + (size_t)b * CIN_D * HW;

    #pragma unroll
    for (int cc = 0; cc < 4; cc++)
        stage_patch16(sp[0] + cc * SPA, xb + (size_t)cc * HW, bx, by, tid);
    CP_COMMIT();

    __syncthreads();

    ull acc2[5][4];
    #pragma unroll
    for (int q = 0; q < 5; q++) {
        ull bv = pack2(sb[2*q], sb[2*q+1]);
        #pragma unroll
        for (int px = 0; px < 4; px++) acc2[q][px] = bv;
    }

    for (int cb = 0; cb < 16; cb++) {
        int cur = cb & 1;
        CP_WAIT0();
        __syncthreads();
        if (cb + 1 < 16) {
            int cn = (cb + 1) * 4;
            #pragma unroll
            for (int cc = 0; cc < 4; cc++)
                stage_patch16(sp[cur ^ 1] + cc * SPA, xb + (size_t)(cn + cc) * HW, bx, by, tid);
        }
        CP_COMMIT();
        int c0 = cb * 4;
        #pragma unroll
        for (int cc = 0; cc < 4; cc++)
            conv_accum_o(acc2, sp[cur] + cc * SPA, sw + (c0 + cc) * 108, tx, ty);
    }

    if (y < Hh) {
        const int p = y * Ww + x0;
        #pragma unroll
        for (int lo = 0; lo < 9; lo++) {
            int oc = base + lo;
            float o4[4];
            #pragma unroll
            for (int px = 0; px < 4; px++) {
                float2 u = unpack2(acc2[lo >> 1][px]);
                o4[px] = (lo & 1) ? u.y : u.x;
            }
            if (oc >= 18) {
                #pragma unroll
                for (int px = 0; px < 4; px++) o4[px] = 2.f * sig_(o4[px]);
            }
            *(float4*)(g_om + ((size_t)b * 27 + oc) * HW + p) = *(float4*)o4;
        }
    }
}

// ---------------------------------------------------------------------------
// Modulated deformable conv. block (32,9)=288 threads, tile 32x9.
// grid (10, 20, 2) = 400 blocks -> single wave at 3 CTAs/SM.
// ---------------------------------------------------------------------------
__global__ __launch_bounds__(288, 3)
void deform_kernel(const float* __restrict__ def_w,
                   const float* __restrict__ def_b)
{
    __shared__ __align__(16) float swd[NK * CIN_D * 9];
    __shared__ float sb[NK];

    const int bx = blockIdx.x * 32, by = blockIdx.y * 9;
    const int b = blockIdx.z;
    const int tx = threadIdx.x, ty = threadIdx.y;
    const int tid = ty * 32 + tx;

    for (int i = tid; i < NK * CIN_D * 9; i += 288) {
        int o = i / 576, rest = i - o * 576;
        swd[rest * 16 + o] = def_w[i];
    }
    if (tid < NK) sb[tid] = def_b[tid];
    __syncthreads();

    const int x = bx + tx, y = by + ty;
    if (y >= Hh) return;
    const int p = y * Ww + x;

    const float* xb = g_hs + (size_t)b * CIN_D * HW;
    const float* om = g_om + (size_t)b * 27 * HW;

    ull acc2[8];
    #pragma unroll
    for (int q = 0; q < 8; q++) acc2[q] = pack2(sb[2*q], sb[2*q+1]);

    #pragma unroll
    for (int j = 0; j < 9; j++) {
        int ky = j / 3, kx = j - ky * 3;
        float dy = om[(2 * j) * HW + p];
        float dx = om[(2 * j + 1) * HW + p];
        float m  = om[(18 + j) * HW + p];
        float py = (float)(y - 1 + ky) + dy;
        float px_ = (float)(x - 1 + kx) + dx;
        float y0f = floorf(py), x0f = floorf(px_);
        float wy = py - y0f, wx = px_ - x0f;
        int y0 = (int)y0f, x0 = (int)x0f;
        int y1 = y0 + 1,   x1 = x0 + 1;
        float vy0 = (y0 >= 0 && y0 < Hh) ? 1.f : 0.f;
        float vy1 = (y1 >= 0 && y1 < Hh) ? 1.f : 0.f;
        float vx0 = (x0 >= 0 && x0 < Ww) ? 1.f : 0.f;
        float vx1 = (x1 >= 0 && x1 < Ww) ? 1.f : 0.f;
        int y0c = min(max(y0, 0), Hh - 1), y1c = min(max(y1, 0), Hh - 1);
        int x0c = min(max(x0, 0), Ww - 1), x1c = min(max(x1, 0), Ww - 1);
        float w00 = (1.f - wy) * (1.f - wx) * vy0 * vx0 * m;
        float w01 = (1.f - wy) * wx         * vy0 * vx1 * m;
        float w10 = wy * (1.f - wx)         * vy1 * vx0 * m;
        float w11 = wy * wx                 * vy1 * vx1 * m;
        int o00 = y0c * Ww + x0c, o01 = y0c * Ww + x1c;
        int o10 = y1c * Ww + x0c, o11 = y1c * Ww + x1c;

        #pragma unroll 4
        for (int c = 0; c < CIN_D; c++) {
            const float* pc_ = xb + (size_t)c * HW;
            float s = w00 * pc_[o00] + w01 * pc_[o01]
                    + w10 * pc_[o10] + w11 * pc_[o11];
            ull ss = pack2(s, s);
            const ulonglong2* w2 = (const ulonglong2*)(swd + (c * 9 + j) * 16);
            ulonglong2 wa = w2[0], wb = w2[1], wc2 = w2[2], wd = w2[3];
            ffma2(acc2[0], ss, wa.x); ffma2(acc2[1], ss, wa.y);
            ffma2(acc2[2], ss, wb.x); ffma2(acc2[3], ss, wb.y);
            ffma2(acc2[4], ss, wc2.x); ffma2(acc2[5], ss, wc2.y);
            ffma2(acc2[6], ss, wd.x); ffma2(acc2[7], ss, wd.y);
        }
    }

    #pragma unroll
    for (int q = 0; q < 8; q++) {
        float2 u = unpack2(acc2[q]);
        g_def[((size_t)b * NK + 2*q    ) * HW + p] = u.x;
        g_def[((size_t)b * NK + 2*q + 1) * HW + p] = u.y;
    }
}

// ---------------------------------------------------------------------------
// Output conv 16 -> 48 + pixel shuffle + clip. (R13 version, 2px, 3 CTAs/SM)
// ---------------------------------------------------------------------------
__global__ __launch_bounds__(256, 3)
void outconv_kernel(const float* __restrict__ out_w,
                    const float* __restrict__ out_b,
                    float* __restrict__ out)
{
    __shared__ __align__(16) float sw[16 * 144];
    __shared__ __align__(16) float sp[2][4 * SPA2];
    __shared__ float sb[16];

    const int tx = threadIdx.x, ty = threadIdx.y;
    const int tid = ty * 32 + tx;
    const int bz = blockIdx.z;
    const int b = bz / 3, g3 = bz - b * 3;
    const int base = g3 * 16;
    const int bx = blockIdx.x * LTW, by = blockIdx.y * LTH2;
    const int x0 = bx + tx * 2, y = by + ty;

    for (int i = tid; i < 16 * 144; i += 256) {
        int lo = i / 144, rest = i - lo * 144;
        sw[rest * 16 + lo] = out_w[(size_t)(base + lo) * 144 + rest];
    }
    if (tid < 16) sb[tid] = out_b[base + tid];

    const float* xb = g_def + (size_t)b * NK * HW;

    #pragma unroll
    for (int cc = 0; cc < 4; cc++)
        stage_patch16_8(sp[0] + cc * SPA2, xb + (size_t)cc * HW, bx, by, tid);
    CP_COMMIT();

    __syncthreads();

    ull acc2[8][2];
    #pragma unroll
    for (int q = 0; q < 8; q++) {
        ull bv = pack2(sb[2*q], sb[2*q+1]);
        acc2[q][0] = bv; acc2[q][1] = bv;
    }

    for (int cb = 0; cb < 4; cb++) {
        int cur = cb & 1;
        CP_WAIT0();
        __syncthreads();
        if (cb + 1 < 4) {
            int cn = (cb + 1) * 4;
            #pragma unroll
            for (int cc = 0; cc < 4; cc++)
                stage_patch16_8(sp[cur ^ 1] + cc * SPA2, xb + (size_t)(cn + cc) * HW, bx, by, tid);
        }
        CP_COMMIT();
        int c0 = cb * 4;
        #pragma unroll
        for (int cc = 0; cc < 4; cc++)
            conv_accum_p2(acc2, sp[cur] + cc * SPA2, sw + (c0 + cc) * 144, tx, ty);
    }

    if (y < Hh) {
        #pragma unroll
        for (int lo = 0; lo < 16; lo++) {
            int oc = base + lo;
            int cch = oc >> 4, rem = oc & 15;
            int r1 = rem >> 2, r2 = rem & 3;
            float2 u = unpack2(acc2[lo >> 1][0]);
            float2 u2 = unpack2(acc2[lo >> 1][1]);
            float v0 = (lo & 1) ? u.y : u.x;
            float v1 = (lo & 1) ? u2.y : u2.x;
            v0 = fminf(fmaxf(v0, 0.f), 255.f);
            v1 = fminf(fmaxf(v1, 0.f), 255.f);
            size_t rowbase = (((size_t)b * NC + cch) * (Hh * SCALE) + (y * SCALE + r1))
                             * (size_t)(Ww * SCALE);
            out[rowbase + (x0 * SCALE + r2)] = v0;
            out[rowbase + ((x0 + 1) * SCALE + r2)] = v1;
        }
    }
}

// ---------------------------------------------------------------------------
extern "C" void kernel_launch(void* const* d_in, const int* in_sizes, int n_in,
                              void* d_out, int out_size)
{
    const float* X      = (const float*)d_in[0];
    const float* lstm_w = (const float*)d_in[1];
    const float* lstm_b = (const float*)d_in[2];
    const float* W_ci   = (const float*)d_in[3];
    const float* W_cf   = (const float*)d_in[4];
    const float* W_co   = (const float*)d_in[5];
    const float* off_w  = (const float*)d_in[6];
    const float* off_b  = (const float*)d_in[7];
    const float* mod_w  = (const float*)d_in[8];
    const float* mod_b  = (const float*)d_in[9];
    const float* def_w  = (const float*)d_in[10];
    const float* def_b  = (const float*)d_in[11];
    const float* out_w  = (const float*)d_in[12];
    const float* out_b  = (const float*)d_in[13];
    float* out = (float*)d_out;

    dim3 blk16(16, 16);
    dim3 grid_lstm(Ww / LTW, (Hh + LTH - 1) / LTH, Bn * 8);

    dim3 grid_om(Ww / LTW, (Hh + LTH - 1) / LTH, Bn * 3);

    dim3 blk32x8(32, 8);
    dim3 grid_oc8(Ww / LTW, (Hh + LTH2 - 1) / LTH2, Bn * 3);

    for (int t = 0; t < Tt; t++)
        lstm_step_kernel<<<grid_lstm, blk16>>>(X, lstm_w, lstm_b, W_ci, W_cf, W_co, t);

    offmask_kernel<<<grid_om, blk16>>>(off_w, off_b, mod_w, mod_b);

    dim3 blk32x9(32, 9);
    dim3 grid_def(Ww / 32, Hh / 9, Bn);   // (10, 20, 2) = 400 blocks
    deform_kernel<<<grid_def, blk32x9>>>(def_w, def_b);

    outconv_kernel<<<grid_oc8, blk32x8>>>(out_w, out_b, out);
}